// round 14
// baseline (speedup 1.0000x reference)
#include <cuda_runtime.h>

#define NUM_HEADS 4
#define D 100
#define D4 25
#define NW 39
#define NT 160
#define TILE_FLOATS 4000
#define TILE_VEC4 1000
#define C_ABS 0.5384615384615384f   // 0.35/0.65 : leaky(p) = 0.65*(p + C_ABS*|p|)
#define C_SCL 0.65f

__global__ __launch_bounds__(NT, 9)
void tse_kernel(const float* __restrict__ x,
                const float* __restrict__ w_att,
                const float* __restrict__ b_att,
                float* __restrict__ out,
                int n_groups)
{
    __shared__ float4 s_wa4[NUM_HEADS * D4];    // 1.6 KB
    __shared__ float4 s_ba4[NUM_HEADS * D4];    // 1.6 KB
    __shared__ float4 s_part[NW * D4];          // 15.6 KB: [n][j] -> {h0..h3}
    __shared__ float4 s_e4[NW];
    __shared__ float  s_inv[NUM_HEADS];
    __shared__ int    s_nz;

    const int t = threadIdx.x;
    const int g = blockIdx.x;
    if (g >= n_groups) return;

    // ---- phase 0: params -> smem (L2-hot), init ----
    if (t == 0) s_nz = 0;
    if (t < NUM_HEADS * D4) {
        s_wa4[t] = reinterpret_cast<const float4*>(w_att)[t];
        s_ba4[t] = reinterpret_cast<const float4*>(b_att)[t];
    }
    __syncthreads();

    const float4* __restrict__ gx4 =
        reinterpret_cast<const float4*>(x + (size_t)g * TILE_FLOATS);

    // ---- stage A: partial scores straight from GLOBAL (coalesced 25-lane rows).
    //      Doubles as the nonzero scan (covers all 40 rows x 100 cols). ----
    const int jp = t % D4;                  // float4 column
    const int nr = t / D4;                  // row class 0..5 (t<150)
    bool flag = false;
    if (t < 150) {
        const float4 ty = gx4[jp];          // type row (row 0)
        flag = (ty.x != 0.f) | (ty.y != 0.f) | (ty.z != 0.f) | (ty.w != 0.f);
        #pragma unroll
        for (int k = 0; k < 7; ++k) {
            const int n = nr + 6 * k;
            if (n < NW) {
                float4 w = gx4[(n + 1) * D4 + jp];
                flag |= (w.x != 0.f) | (w.y != 0.f) | (w.z != 0.f) | (w.w != 0.f);
                float p, q, a0, a1, a2, a3;
                float4 A, B;
                A = s_wa4[0 * D4 + jp]; B = s_ba4[0 * D4 + jp];
                p = fmaf(w.x, A.x, B.x); q = fmaf(C_ABS, fabsf(p), p); a0 = ty.x * q;
                p = fmaf(w.y, A.y, B.y); q = fmaf(C_ABS, fabsf(p), p); a0 = fmaf(ty.y, q, a0);
                p = fmaf(w.z, A.z, B.z); q = fmaf(C_ABS, fabsf(p), p); a0 = fmaf(ty.z, q, a0);
                p = fmaf(w.w, A.w, B.w); q = fmaf(C_ABS, fabsf(p), p); a0 = fmaf(ty.w, q, a0);
                A = s_wa4[1 * D4 + jp]; B = s_ba4[1 * D4 + jp];
                p = fmaf(w.x, A.x, B.x); q = fmaf(C_ABS, fabsf(p), p); a1 = ty.x * q;
                p = fmaf(w.y, A.y, B.y); q = fmaf(C_ABS, fabsf(p), p); a1 = fmaf(ty.y, q, a1);
                p = fmaf(w.z, A.z, B.z); q = fmaf(C_ABS, fabsf(p), p); a1 = fmaf(ty.z, q, a1);
                p = fmaf(w.w, A.w, B.w); q = fmaf(C_ABS, fabsf(p), p); a1 = fmaf(ty.w, q, a1);
                A = s_wa4[2 * D4 + jp]; B = s_ba4[2 * D4 + jp];
                p = fmaf(w.x, A.x, B.x); q = fmaf(C_ABS, fabsf(p), p); a2 = ty.x * q;
                p = fmaf(w.y, A.y, B.y); q = fmaf(C_ABS, fabsf(p), p); a2 = fmaf(ty.y, q, a2);
                p = fmaf(w.z, A.z, B.z); q = fmaf(C_ABS, fabsf(p), p); a2 = fmaf(ty.z, q, a2);
                p = fmaf(w.w, A.w, B.w); q = fmaf(C_ABS, fabsf(p), p); a2 = fmaf(ty.w, q, a2);
                A = s_wa4[3 * D4 + jp]; B = s_ba4[3 * D4 + jp];
                p = fmaf(w.x, A.x, B.x); q = fmaf(C_ABS, fabsf(p), p); a3 = ty.x * q;
                p = fmaf(w.y, A.y, B.y); q = fmaf(C_ABS, fabsf(p), p); a3 = fmaf(ty.y, q, a3);
                p = fmaf(w.z, A.z, B.z); q = fmaf(C_ABS, fabsf(p), p); a3 = fmaf(ty.z, q, a3);
                p = fmaf(w.w, A.w, B.w); q = fmaf(C_ABS, fabsf(p), p); a3 = fmaf(ty.w, q, a3);
                s_part[n * D4 + jp] = make_float4(a0, a1, a2, a3);
            }
        }
    }
    unsigned any = __ballot_sync(0xffffffffu, flag);
    if ((t & 31) == 0 && any) atomicOr(&s_nz, 1);
    __syncthreads();

    // ---- stage B: score(h,n) = sum_j part[n][j][h] ----
    if (t < NUM_HEADS * NW) {
        const float* pf = (const float*)s_part;
        const float* row = pf + (t >> 2) * 100 + (t & 3);
        float s0 = 0.f, s1 = 0.f;
        #pragma unroll
        for (int j = 0; j < 24; j += 2) {
            s0 += row[4 * j];
            s1 += row[4 * (j + 1)];
        }
        s0 += row[4 * 24];
        ((float*)s_e4)[t] = __expf(C_SCL * (s0 + s1));
    }
    __syncthreads();

    // ---- phase 3: per-head denominators, warp h reduces head h ----
    if (t < 4 * 32) {
        const int h = t >> 5, lane = t & 31;
        const float* ef = (const float*)s_e4;
        float v = (lane < NW) ? ef[lane * 4 + h] : 0.f;
        if (lane < NW - 32) v += ef[(lane + 32) * 4 + h];
        #pragma unroll
        for (int off = 16; off; off >>= 1)
            v += __shfl_down_sync(0xffffffffu, v, off);
        if (lane == 0) s_inv[h] = __fdividef(1.f, v);
    }
    __syncthreads();

    // ---- phase 4: 25-thread register tile; words re-read from L1/L2-hot global ----
    if (t < D4) {
        float4 o0 = make_float4(0.f, 0.f, 0.f, 0.f);
        float4 o1 = o0, o2 = o0, o3 = o0;
        #pragma unroll 13
        for (int n = 0; n < NW; ++n) {
            float4 w = gx4[(n + 1) * D4 + t];   // coalesced 400B, cache-hot
            float4 e = s_e4[n];
            o0.x = fmaf(e.x, w.x, o0.x); o0.y = fmaf(e.x, w.y, o0.y);
            o0.z = fmaf(e.x, w.z, o0.z); o0.w = fmaf(e.x, w.w, o0.w);
            o1.x = fmaf(e.y, w.x, o1.x); o1.y = fmaf(e.y, w.y, o1.y);
            o1.z = fmaf(e.y, w.z, o1.z); o1.w = fmaf(e.y, w.w, o1.w);
            o2.x = fmaf(e.z, w.x, o2.x); o2.y = fmaf(e.z, w.y, o2.y);
            o2.z = fmaf(e.z, w.z, o2.z); o2.w = fmaf(e.z, w.w, o2.w);
            o3.x = fmaf(e.w, w.x, o3.x); o3.y = fmaf(e.w, w.y, o3.y);
            o3.z = fmaf(e.w, w.z, o3.z); o3.w = fmaf(e.w, w.w, o3.w);
        }
        float4* __restrict__ go4 =
            reinterpret_cast<float4*>(out + (size_t)g * (NUM_HEADS * D));
        const float4 zero = make_float4(0.f, 0.f, 0.f, 0.f);
        if (s_nz) {
            float i0 = s_inv[0], i1 = s_inv[1], i2 = s_inv[2], i3 = s_inv[3];
            go4[0 * D4 + t] = make_float4(o0.x * i0, o0.y * i0, o0.z * i0, o0.w * i0);
            go4[1 * D4 + t] = make_float4(o1.x * i1, o1.y * i1, o1.z * i1, o1.w * i1);
            go4[2 * D4 + t] = make_float4(o2.x * i2, o2.y * i2, o2.z * i2, o2.w * i2);
            go4[3 * D4 + t] = make_float4(o3.x * i3, o3.y * i3, o3.z * i3, o3.w * i3);
        } else {
            go4[0 * D4 + t] = zero; go4[1 * D4 + t] = zero;
            go4[2 * D4 + t] = zero; go4[3 * D4 + t] = zero;
        }
    }
}

extern "C" void kernel_launch(void* const* d_in, const int* in_sizes, int n_in,
                              void* d_out, int out_size)
{
    const float* x     = (const float*)d_in[0];
    const float* w_att = (const float*)d_in[1];
    const float* b_att = (const float*)d_in[2];
    float* out = (float*)d_out;

    int n_groups = in_sizes[0] / TILE_FLOATS;   // B*T*E = 4800
    tse_kernel<<<n_groups, NT>>>(x, w_att, b_att, out, n_groups);
}

// round 15
// speedup vs baseline: 1.6881x; 1.6881x over previous
#include <cuda_runtime.h>

#define NUM_HEADS 4
#define D4 25
#define NW 39
#define NT 128
#define WPB 4               // independent warps (groups) per block
#define TILE_FLOATS 4000
#define C_ABS 0.5384615384615384f   // 0.35/0.65 : leaky(p) = 0.65*(p + C_ABS*|p|)
#define C_SCL 0.65f

__global__ __launch_bounds__(NT, 6)
void tse_kernel(const float* __restrict__ x,
                const float* __restrict__ w_att,
                const float* __restrict__ b_att,
                float* __restrict__ out,
                int n_groups)
{
    __shared__ float4 s_e[WPB][NW + 1];      // per-warp score/exp table (2.5 KB)

    const int lane = threadIdx.x & 31;
    const int warp = threadIdx.x >> 5;
    const int g = blockIdx.x * WPB + warp;
    if (g >= n_groups) return;               // warp-uniform exit; no block barriers anywhere

    const bool act = lane < D4;
    const int  jp  = act ? lane : 0;         // clamped: no OOB, inactive lanes mirror lane 0

    const float4* __restrict__ gx4 =
        reinterpret_cast<const float4*>(x + (size_t)g * TILE_FLOATS);

    // ---- params -> registers (lane = fixed column jp; L1/L2-hot after warp 0) ----
    const float4* wAv = reinterpret_cast<const float4*>(w_att);
    const float4* bAv = reinterpret_cast<const float4*>(b_att);
    const float4 wa0 = wAv[0 * D4 + jp], ba0 = bAv[0 * D4 + jp];
    const float4 wa1 = wAv[1 * D4 + jp], ba1 = bAv[1 * D4 + jp];
    const float4 wa2 = wAv[2 * D4 + jp], ba2 = bAv[2 * D4 + jp];
    const float4 wa3 = wAv[3 * D4 + jp], ba3 = bAv[3 * D4 + jp];

    float4 ty = gx4[jp];                     // type row
    if (!act) ty = make_float4(0.f, 0.f, 0.f, 0.f);   // kills inactive contributions
    bool flag = act && ((ty.x != 0.f) | (ty.y != 0.f) | (ty.z != 0.f) | (ty.w != 0.f));

    // ---- phase 1: scores. One coalesced LDG.128 row per word; xor-butterfly reduce. ----
    #pragma unroll 3
    for (int n = 0; n < NW; ++n) {
        float4 w = gx4[(n + 1) * D4 + jp];
        if (act) flag |= (w.x != 0.f) | (w.y != 0.f) | (w.z != 0.f) | (w.w != 0.f);
        float p, q, a0, a1, a2, a3;
        p = fmaf(w.x, wa0.x, ba0.x); q = fmaf(C_ABS, fabsf(p), p); a0 = ty.x * q;
        p = fmaf(w.y, wa0.y, ba0.y); q = fmaf(C_ABS, fabsf(p), p); a0 = fmaf(ty.y, q, a0);
        p = fmaf(w.z, wa0.z, ba0.z); q = fmaf(C_ABS, fabsf(p), p); a0 = fmaf(ty.z, q, a0);
        p = fmaf(w.w, wa0.w, ba0.w); q = fmaf(C_ABS, fabsf(p), p); a0 = fmaf(ty.w, q, a0);
        p = fmaf(w.x, wa1.x, ba1.x); q = fmaf(C_ABS, fabsf(p), p); a1 = ty.x * q;
        p = fmaf(w.y, wa1.y, ba1.y); q = fmaf(C_ABS, fabsf(p), p); a1 = fmaf(ty.y, q, a1);
        p = fmaf(w.z, wa1.z, ba1.z); q = fmaf(C_ABS, fabsf(p), p); a1 = fmaf(ty.z, q, a1);
        p = fmaf(w.w, wa1.w, ba1.w); q = fmaf(C_ABS, fabsf(p), p); a1 = fmaf(ty.w, q, a1);
        p = fmaf(w.x, wa2.x, ba2.x); q = fmaf(C_ABS, fabsf(p), p); a2 = ty.x * q;
        p = fmaf(w.y, wa2.y, ba2.y); q = fmaf(C_ABS, fabsf(p), p); a2 = fmaf(ty.y, q, a2);
        p = fmaf(w.z, wa2.z, ba2.z); q = fmaf(C_ABS, fabsf(p), p); a2 = fmaf(ty.z, q, a2);
        p = fmaf(w.w, wa2.w, ba2.w); q = fmaf(C_ABS, fabsf(p), p); a2 = fmaf(ty.w, q, a2);
        p = fmaf(w.x, wa3.x, ba3.x); q = fmaf(C_ABS, fabsf(p), p); a3 = ty.x * q;
        p = fmaf(w.y, wa3.y, ba3.y); q = fmaf(C_ABS, fabsf(p), p); a3 = fmaf(ty.y, q, a3);
        p = fmaf(w.z, wa3.z, ba3.z); q = fmaf(C_ABS, fabsf(p), p); a3 = fmaf(ty.z, q, a3);
        p = fmaf(w.w, wa3.w, ba3.w); q = fmaf(C_ABS, fabsf(p), p); a3 = fmaf(ty.w, q, a3);
        #pragma unroll
        for (int off = 16; off; off >>= 1) {
            a0 += __shfl_xor_sync(0xffffffffu, a0, off);
            a1 += __shfl_xor_sync(0xffffffffu, a1, off);
            a2 += __shfl_xor_sync(0xffffffffu, a2, off);
            a3 += __shfl_xor_sync(0xffffffffu, a3, off);
        }
        if (lane == 0) s_e[warp][n] = make_float4(a0, a1, a2, a3);
    }
    const unsigned nzmask = __ballot_sync(0xffffffffu, flag);
    __syncwarp();

    // ---- phase 2: exp + denominators (all 32 lanes; lane n handles n and n+32) ----
    float4 ps;
    {
        float4 v = s_e[warp][lane];          // lane 0..31, all < NW
        float4 e;
        e.x = __expf(C_SCL * v.x); e.y = __expf(C_SCL * v.y);
        e.z = __expf(C_SCL * v.z); e.w = __expf(C_SCL * v.w);
        s_e[warp][lane] = e;
        ps = e;
        if (lane < NW - 32) {
            v = s_e[warp][32 + lane];
            e.x = __expf(C_SCL * v.x); e.y = __expf(C_SCL * v.y);
            e.z = __expf(C_SCL * v.z); e.w = __expf(C_SCL * v.w);
            s_e[warp][32 + lane] = e;
            ps.x += e.x; ps.y += e.y; ps.z += e.z; ps.w += e.w;
        }
    }
    #pragma unroll
    for (int off = 16; off; off >>= 1) {
        ps.x += __shfl_xor_sync(0xffffffffu, ps.x, off);
        ps.y += __shfl_xor_sync(0xffffffffu, ps.y, off);
        ps.z += __shfl_xor_sync(0xffffffffu, ps.z, off);
        ps.w += __shfl_xor_sync(0xffffffffu, ps.w, off);
    }
    const float i0 = __fdividef(1.f, ps.x);
    const float i1 = __fdividef(1.f, ps.y);
    const float i2 = __fdividef(1.f, ps.z);
    const float i3 = __fdividef(1.f, ps.w);
    __syncwarp();

    // ---- phase 3: output tile. lane jp owns d = 4jp..4jp+3 for all heads. ----
    float4 o0 = make_float4(0.f, 0.f, 0.f, 0.f);
    float4 o1 = o0, o2 = o0, o3 = o0;
    #pragma unroll 3
    for (int n = 0; n < NW; ++n) {
        float4 w = gx4[(n + 1) * D4 + jp];   // L1-hot re-read (touched in phase 1)
        float4 e = s_e[warp][n];
        o0.x = fmaf(e.x, w.x, o0.x); o0.y = fmaf(e.x, w.y, o0.y);
        o0.z = fmaf(e.x, w.z, o0.z); o0.w = fmaf(e.x, w.w, o0.w);
        o1.x = fmaf(e.y, w.x, o1.x); o1.y = fmaf(e.y, w.y, o1.y);
        o1.z = fmaf(e.y, w.z, o1.z); o1.w = fmaf(e.y, w.w, o1.w);
        o2.x = fmaf(e.z, w.x, o2.x); o2.y = fmaf(e.z, w.y, o2.y);
        o2.z = fmaf(e.z, w.z, o2.z); o2.w = fmaf(e.z, w.w, o2.w);
        o3.x = fmaf(e.w, w.x, o3.x); o3.y = fmaf(e.w, w.y, o3.y);
        o3.z = fmaf(e.w, w.z, o3.z); o3.w = fmaf(e.w, w.w, o3.w);
    }
    if (act) {
        float4* __restrict__ go4 =
            reinterpret_cast<float4*>(out + (size_t)g * (NUM_HEADS * 4 * D4));
        if (nzmask) {
            go4[0 * D4 + jp] = make_float4(o0.x * i0, o0.y * i0, o0.z * i0, o0.w * i0);
            go4[1 * D4 + jp] = make_float4(o1.x * i1, o1.y * i1, o1.z * i1, o1.w * i1);
            go4[2 * D4 + jp] = make_float4(o2.x * i2, o2.y * i2, o2.z * i2, o2.w * i2);
            go4[3 * D4 + jp] = make_float4(o3.x * i3, o3.y * i3, o3.z * i3, o3.w * i3);
        } else {
            const float4 zero = make_float4(0.f, 0.f, 0.f, 0.f);
            go4[0 * D4 + jp] = zero; go4[1 * D4 + jp] = zero;
            go4[2 * D4 + jp] = zero; go4[3 * D4 + jp] = zero;
        }
    }
}

extern "C" void kernel_launch(void* const* d_in, const int* in_sizes, int n_in,
                              void* d_out, int out_size)
{
    const float* x     = (const float*)d_in[0];
    const float* w_att = (const float*)d_in[1];
    const float* b_att = (const float*)d_in[2];
    float* out = (float*)d_out;

    int n_groups = in_sizes[0] / TILE_FLOATS;        // 4800
    int n_blocks = (n_groups + WPB - 1) / WPB;       // 1200
    tse_kernel<<<n_blocks, NT>>>(x, w_att, b_att, out, n_groups);
}